// round 6
// baseline (speedup 1.0000x reference)
#include <cuda_runtime.h>
#include <math.h>

#define N_NODES 50000
#define N_EDGES 800000
#define G_GRAPHS 8
#define ED_DIM 32

typedef unsigned long long u64;

__device__ __forceinline__ u64 pack2s(float a) {
    u64 r; asm("mov.b64 %0,{%1,%1};" : "=l"(r) : "f"(a)); return r;
}
__device__ __forceinline__ float2 unpk(u64 v) {
    float2 f; asm("mov.b64 {%0,%1},%2;" : "=f"(f.x), "=f"(f.y) : "l"(v)); return f;
}
__device__ __forceinline__ u64 ffma2(u64 a, u64 b, u64 c) {
    u64 d; asm("fma.rn.f32x2 %0,%1,%2,%3;" : "=l"(d) : "l"(a), "l"(b), "l"(c)); return d;
}
__device__ __forceinline__ u64 fmul2(u64 a, u64 b) {
    u64 d; asm("mul.rn.f32x2 %0,%1,%2;" : "=l"(d) : "l"(a), "l"(b)); return d;
}
__device__ __forceinline__ u64 fadd2(u64 a, u64 b) {
    u64 d; asm("add.rn.f32x2 %0,%1,%2;" : "=l"(d) : "l"(a), "l"(b)); return d;
}

// ---------------- scratch ----------------
__device__ float d_xl1[N_NODES * 128];
__device__ float d_xr1[N_NODES * 128];
__device__ float d_h1 [N_NODES * 128];
__device__ float d_xl2[N_NODES * 192];
__device__ float d_xr2[N_NODES * 192];
__device__ float d_h2 [N_NODES * 192];
__device__ int   d_rowptr[N_NODES + 1];
__device__ int   d_counts[N_NODES];
__device__ int   d_cursor[N_NODES];
__device__ int2  d_csr[N_EDGES];     // (src, eid) grouped by dst
__device__ float d_pool[G_GRAPHS * 192];

__device__ __forceinline__ float lr2(float x)  { return x > 0.f ? x : 0.2f  * x; }
__device__ __forceinline__ float lr01(float x) { return x > 0.f ? x : 0.01f * x; }

// ---------------- CSR build ----------------
__global__ void zero_kernel() {
    int i = blockIdx.x * blockDim.x + threadIdx.x;
    if (i < N_NODES) { d_counts[i] = 0; d_cursor[i] = 0; }
    if (i < G_GRAPHS * 192) d_pool[i] = 0.f;
}

__global__ void hist_kernel(const int* __restrict__ dst) {
    int e = blockIdx.x * blockDim.x + threadIdx.x;
    if (e < N_EDGES) atomicAdd(&d_counts[dst[e]], 1);
}

__global__ void scan_kernel() {
    __shared__ int sh[1024];
    int t = threadIdx.x;
    const int CH = (N_NODES + 1023) / 1024;
    int lo = t * CH;
    int hi = min(lo + CH, N_NODES);
    int s = 0;
    for (int i = lo; i < hi; i++) s += d_counts[i];
    sh[t] = s;
    __syncthreads();
    for (int off = 1; off < 1024; off <<= 1) {
        int v = (t >= off) ? sh[t - off] : 0;
        __syncthreads();
        sh[t] += v;
        __syncthreads();
    }
    int run = (t > 0) ? sh[t - 1] : 0;
    for (int i = lo; i < hi; i++) { d_rowptr[i] = run; run += d_counts[i]; }
    if (t == 0) d_rowptr[N_NODES] = N_EDGES;
}

__global__ void scatter_kernel(const int* __restrict__ src, const int* __restrict__ dst) {
    int e = blockIdx.x * blockDim.x + threadIdx.x;
    if (e < N_EDGES) {
        int d = dst[e];
        int p = atomicAdd(&d_cursor[d], 1);
        d_csr[d_rowptr[d] + p] = make_int2(src[e], e);
    }
}

// ---------------- GEMM: Y[M,Ncols] = X[M,128] @ W[128,Ncols] + bias ----------------
__global__ __launch_bounds__(256) void gemm_k128(
    const float* __restrict__ Xin, int useH1,
    const float* __restrict__ W, const float* __restrict__ bias,
    int outSel, int M, int Ncols)
{
    const float* X = useH1 ? d_h1 : Xin;
    float* Y = (outSel == 0) ? d_xl1 : (outSel == 1) ? d_xr1 : (outSel == 2) ? d_xl2 : d_xr2;

    __shared__ float XsT[32 * 132];  // [k][m]
    __shared__ float Ws [32 * 68];   // [k][n]

    int tid = threadIdx.x;
    int tx = tid & 15, ty = tid >> 4;
    int m0 = blockIdx.x * 128, n0 = blockIdx.y * 64;

    u64 acc[8][2] = {};

    for (int k0 = 0; k0 < 128; k0 += 32) {
        for (int gi = tid; gi < 1024; gi += 256) {
            int m = gi >> 3, k4 = gi & 7;
            int row = m0 + m;
            float4 v = make_float4(0.f, 0.f, 0.f, 0.f);
            if (row < M) v = *(const float4*)&X[(size_t)row * 128 + k0 + k4 * 4];
            XsT[(k4 * 4 + 0) * 132 + m] = v.x;
            XsT[(k4 * 4 + 1) * 132 + m] = v.y;
            XsT[(k4 * 4 + 2) * 132 + m] = v.z;
            XsT[(k4 * 4 + 3) * 132 + m] = v.w;
        }
        for (int gi = tid; gi < 512; gi += 256) {
            int kk = gi >> 4, n4 = gi & 15;
            float4 v = *(const float4*)&W[(size_t)(k0 + kk) * Ncols + n0 + n4 * 4];
            *(float4*)&Ws[kk * 68 + n4 * 4] = v;
        }
        __syncthreads();
        #pragma unroll 8
        for (int kk = 0; kk < 32; kk++) {
            ulonglong2 w2 = *(const ulonglong2*)&Ws[kk * 68 + tx * 4];
            float4 a03 = *(const float4*)&XsT[kk * 132 + ty * 8];
            float4 a47 = *(const float4*)&XsT[kk * 132 + ty * 8 + 4];
            float av[8] = {a03.x, a03.y, a03.z, a03.w, a47.x, a47.y, a47.z, a47.w};
            #pragma unroll
            for (int i = 0; i < 8; i++) {
                u64 a2 = pack2s(av[i]);
                acc[i][0] = ffma2(a2, w2.x, acc[i][0]);
                acc[i][1] = ffma2(a2, w2.y, acc[i][1]);
            }
        }
        __syncthreads();
    }

    float4 bv = *(const float4*)&bias[n0 + tx * 4];
    #pragma unroll
    for (int i = 0; i < 8; i++) {
        int row = m0 + ty * 8 + i;
        if (row < M) {
            float2 p0 = unpk(acc[i][0]), p1 = unpk(acc[i][1]);
            float4 o = make_float4(p0.x + bv.x, p0.y + bv.y, p1.x + bv.z, p1.y + bv.w);
            *(float4*)&Y[(size_t)row * Ncols + n0 + tx * 4] = o;
        }
    }
}

// ---------------- GATv2 conv: fused warp-per-node, software-pipelined gathers -----
// Loads for edge-group g+1 are issued BEFORE group g's 32-k matvec so the
// DRAM/L2 gather latency hides behind compute instead of stalling the matvec.
// All __shfl_sync calls are warp-uniform in control flow (guards gate only the
// loads; every lane participates in every shfl).
template <int HC>
__global__ __launch_bounds__(256, 2) void conv_kernel(
    const float* __restrict__ ea, const float* __restrict__ We,
    const float* __restrict__ att, const float* __restrict__ bias)
{
    constexpr bool HB = (HC == 192);
    const float* xl = (HC == 128) ? d_xl1 : d_xl2;
    const float* xr = (HC == 128) ? d_xr1 : d_xr2;
    float*       h  = (HC == 128) ? d_h1  : d_h2;

    __shared__ float sWe[32 * HC];
    for (int i = threadIdx.x; i < 32 * HC; i += 256) sWe[i] = We[i];
    __syncthreads();

    const unsigned FULL = 0xffffffffu;
    int warp = threadIdx.x >> 5, lane = threadIdx.x & 31;
    int node = blockIdx.x * 8 + warp;
    if (node >= N_NODES) return;

    int cA = 4 * lane;
    int hA = (lane < 16) ? 0 : 1;
    float attA[4], biasA[4];
    #pragma unroll
    for (int i = 0; i < 4; i++) {
        attA[i]  = att[hA * 64 + 4 * (lane & 15) + i];
        biasA[i] = bias[cA + i];
    }
    float attB[2] = {0.f, 0.f}, biasB[2] = {0.f, 0.f};
    if (HB) {
        attB[0]  = att[128 + 2 * lane + 0];
        attB[1]  = att[128 + 2 * lane + 1];
        biasB[0] = bias[128 + 2 * lane + 0];
        biasB[1] = bias[128 + 2 * lane + 1];
    }

    int r0 = d_rowptr[node], r1 = d_rowptr[node + 1];
    int deg = r1 - r0;

    ulonglong2 xrA = *(const ulonglong2*)&xr[(size_t)node * HC + cA];
    ulonglong2 xlA = *(const ulonglong2*)&xl[(size_t)node * HC + cA];
    u64 xrB = 0, xlB = 0;
    if (HB) {
        xrB = *(const u64*)&xr[(size_t)node * HC + 128 + 2 * lane];
        xlB = *(const u64*)&xl[(size_t)node * HC + 128 + 2 * lane];
    }

    float mA = -1e30f, sA = 0.f;
    u64 accA0 = 0, accA1 = 0;
    float mB = -1e30f, sB = 0.f;
    u64 accB = 0;
    float easum = 0.f;

    for (int base = 0; base < deg; base += 32) {
        int j = base + lane;
        int2 es = (j < deg) ? d_csr[r0 + j] : make_int2(0, 0);
        int nb = min(32, deg - base);   // warp-uniform

        // prefetch buffers for next group
        float nEav[4]; ulonglong2 nXA[4]; u64 nXB[4];
        #pragma unroll
        for (int t = 0; t < 4; t++) {
            int s_t = __shfl_sync(FULL, es.x, t);
            int e_t = __shfl_sync(FULL, es.y, t);
            if (t < nb) {
                nEav[t] = ea[(size_t)e_t * ED_DIM + lane];
                nXA[t]  = *(const ulonglong2*)&xl[(size_t)s_t * HC + cA];
                if (HB) nXB[t] = *(const u64*)&xl[(size_t)s_t * HC + 128 + 2 * lane];
            } else {
                nEav[t] = 0.f; nXA[t].x = nXA[t].y = 0ull; if (HB) nXB[t] = 0ull;
            }
        }

        for (int bu = 0; bu < nb; bu += 4) {
            int cnt = min(4, nb - bu);
            // consume prefetched data
            float eav[4]; ulonglong2 xA[4]; u64 xB[4];
            #pragma unroll
            for (int t = 0; t < 4; t++) {
                eav[t] = nEav[t]; xA[t] = nXA[t];
                if (HB) xB[t] = nXB[t];
                easum += eav[t];
            }
            // issue next group's loads (latency hidden behind matvec below).
            // condition is warp-uniform (nb uniform per warp).
            if (bu + 4 < nb) {
                #pragma unroll
                for (int t = 0; t < 4; t++) {
                    int s_t = __shfl_sync(FULL, es.x, bu + 4 + t);
                    int e_t = __shfl_sync(FULL, es.y, bu + 4 + t);
                    if (bu + 4 + t < nb) {
                        nEav[t] = ea[(size_t)e_t * ED_DIM + lane];
                        nXA[t]  = *(const ulonglong2*)&xl[(size_t)s_t * HC + cA];
                        if (HB) nXB[t] = *(const u64*)&xl[(size_t)s_t * HC + 128 + 2 * lane];
                    } else {
                        nEav[t] = 0.f; nXA[t].x = nXA[t].y = 0ull; if (HB) nXB[t] = 0ull;
                    }
                }
            }

            ulonglong2 vA[4]; u64 vB[4];
            #pragma unroll
            for (int t = 0; t < 4; t++) {
                vA[t].x = fadd2(xA[t].x, xrA.x);
                vA[t].y = fadd2(xA[t].y, xrA.y);
                if (HB) vB[t] = fadd2(xB[t], xrB);
            }
            // ee = ea @ We, packed FFMA2; one shared read serves 4 edges
            #pragma unroll
            for (int k = 0; k < 32; k++) {
                ulonglong2 w = *(const ulonglong2*)&sWe[k * HC + cA];
                u64 wb = 0;
                if (HB) wb = *(const u64*)&sWe[k * HC + 128 + 2 * lane];
                #pragma unroll
                for (int t = 0; t < 4; t++) {
                    u64 a2 = pack2s(__shfl_sync(FULL, eav[t], k));
                    vA[t].x = ffma2(a2, w.x, vA[t].x);
                    vA[t].y = ffma2(a2, w.y, vA[t].y);
                    if (HB) vB[t] = ffma2(a2, wb, vB[t]);
                }
            }
            // alpha + online softmax + weighted accumulate
            #pragma unroll
            for (int t = 0; t < 4; t++) {
                float2 f0 = unpk(vA[t].x), f1 = unpk(vA[t].y);
                float pa = lr2(f0.x) * attA[0] + lr2(f0.y) * attA[1]
                         + lr2(f1.x) * attA[2] + lr2(f1.y) * attA[3];
                pa += __shfl_xor_sync(FULL, pa, 8);
                pa += __shfl_xor_sync(FULL, pa, 4);
                pa += __shfl_xor_sync(FULL, pa, 2);
                pa += __shfl_xor_sync(FULL, pa, 1);
                float pb = 0.f;
                if (HB) {
                    float2 fb = unpk(vB[t]);
                    pb = lr2(fb.x) * attB[0] + lr2(fb.y) * attB[1];
                    pb += __shfl_xor_sync(FULL, pb, 16);
                    pb += __shfl_xor_sync(FULL, pb, 8);
                    pb += __shfl_xor_sync(FULL, pb, 4);
                    pb += __shfl_xor_sync(FULL, pb, 2);
                    pb += __shfl_xor_sync(FULL, pb, 1);
                }
                if (t < cnt) {   // warp-uniform
                    float nm = fmaxf(mA, pa);
                    float sc = __expf(mA - nm);
                    float p  = __expf(pa - nm);
                    sA = sA * sc + p;
                    u64 sc2 = pack2s(sc), p2 = pack2s(p);
                    accA0 = ffma2(accA0, sc2, fmul2(p2, xA[t].x));
                    accA1 = ffma2(accA1, sc2, fmul2(p2, xA[t].y));
                    mA = nm;
                    if (HB) {
                        float nmb = fmaxf(mB, pb);
                        float scb = __expf(mB - nmb);
                        float pB2 = __expf(pb - nmb);
                        sB = sB * scb + pB2;
                        accB = ffma2(accB, pack2s(scb), fmul2(pack2s(pB2), xB[t]));
                        mB = nmb;
                    }
                }
            }
        }
    }

    // ---- self loop: ea_loop = mean of incoming edge attrs (0 if none) ----
    {
        float eal = easum * (1.0f / (float)max(deg, 1));
        u64 v0 = fadd2(xlA.x, xrA.x);
        u64 v1 = fadd2(xlA.y, xrA.y);
        u64 vb = HB ? fadd2(xlB, xrB) : 0ull;
        #pragma unroll
        for (int k = 0; k < 32; k++) {
            u64 a2 = pack2s(__shfl_sync(FULL, eal, k));
            ulonglong2 w = *(const ulonglong2*)&sWe[k * HC + cA];
            v0 = ffma2(a2, w.x, v0);
            v1 = ffma2(a2, w.y, v1);
            if (HB) {
                u64 wb = *(const u64*)&sWe[k * HC + 128 + 2 * lane];
                vb = ffma2(a2, wb, vb);
            }
        }
        float2 f0 = unpk(v0), f1 = unpk(v1);
        float pa = lr2(f0.x) * attA[0] + lr2(f0.y) * attA[1]
                 + lr2(f1.x) * attA[2] + lr2(f1.y) * attA[3];
        pa += __shfl_xor_sync(FULL, pa, 8);
        pa += __shfl_xor_sync(FULL, pa, 4);
        pa += __shfl_xor_sync(FULL, pa, 2);
        pa += __shfl_xor_sync(FULL, pa, 1);
        float nm = fmaxf(mA, pa);
        float sc = __expf(mA - nm);
        float p  = __expf(pa - nm);
        sA = sA * sc + p;
        u64 sc2 = pack2s(sc), p2 = pack2s(p);
        accA0 = ffma2(accA0, sc2, fmul2(p2, xlA.x));
        accA1 = ffma2(accA1, sc2, fmul2(p2, xlA.y));
        if (HB) {
            float2 fb = unpk(vb);
            float pb = lr2(fb.x) * attB[0] + lr2(fb.y) * attB[1];
            pb += __shfl_xor_sync(FULL, pb, 16);
            pb += __shfl_xor_sync(FULL, pb, 8);
            pb += __shfl_xor_sync(FULL, pb, 4);
            pb += __shfl_xor_sync(FULL, pb, 2);
            pb += __shfl_xor_sync(FULL, pb, 1);
            float nmb = fmaxf(mB, pb);
            float scb = __expf(mB - nmb);
            float pB2 = __expf(pb - nmb);
            sB = sB * scb + pB2;
            accB = ffma2(accB, pack2s(scb), fmul2(pack2s(pB2), xlB));
        }
    }

    // ---- write h = lrelu_{0.01}(acc/s + bias) ----
    float invA = 1.0f / sA;
    float2 a0 = unpk(accA0), a1 = unpk(accA1);
    float4 o;
    o.x = lr01(a0.x * invA + biasA[0]);
    o.y = lr01(a0.y * invA + biasA[1]);
    o.z = lr01(a1.x * invA + biasA[2]);
    o.w = lr01(a1.y * invA + biasA[3]);
    *(float4*)&h[(size_t)node * HC + cA] = o;
    if (HB) {
        float invB = 1.0f / sB;
        float2 ab = unpk(accB);
        float2 ob;
        ob.x = lr01(ab.x * invB + biasB[0]);
        ob.y = lr01(ab.y * invB + biasB[1]);
        *(float2*)&h[(size_t)node * HC + 128 + 2 * lane] = ob;
    }
}

// ---------------- global_add_pool ----------------
__global__ void pool_kernel(const int* __restrict__ batch) {
    __shared__ float acc[G_GRAPHS * 192];
    int c = threadIdx.x;  // 0..191
    for (int i = c; i < G_GRAPHS * 192; i += 192) acc[i] = 0.f;
    __syncthreads();
    int per = (N_NODES + gridDim.x - 1) / gridDim.x;
    int lo = blockIdx.x * per;
    int hi = min(lo + per, N_NODES);
    for (int n = lo; n < hi; n++) {
        int b = batch[n];
        acc[b * 192 + c] += d_h2[(size_t)n * 192 + c];
    }
    __syncthreads();
    for (int i = c; i < G_GRAPHS * 192; i += 192) atomicAdd(&d_pool[i], acc[i]);
}

// ---------------- MLP head ----------------
__global__ void mlp_kernel(
    const float* __restrict__ W1, const float* __restrict__ c1,
    const float* __restrict__ W2, const float* __restrict__ c2,
    const float* __restrict__ W3, const float* __restrict__ c3,
    const float* __restrict__ W4, const float* __restrict__ c4,
    const float* __restrict__ W5, const float* __restrict__ c5,
    const float* __restrict__ W6, const float* __restrict__ c6,
    float* __restrict__ out)
{
    __shared__ float sa[G_GRAPHS * 192];
    __shared__ float sb[G_GRAPHS * 64];
    int t = threadIdx.x;
    for (int i = t; i < G_GRAPHS * 192; i += 512) sa[i] = d_pool[i];
    __syncthreads();
    if (t < 512) {
        int i = t >> 6, j = t & 63;
        float v = c1[j];
        for (int k = 0; k < 192; k++) v += sa[i * 192 + k] * W1[k * 64 + j];
        sb[t] = lr01(v);
    }
    __syncthreads();
    if (t < 256) {
        int i = t >> 5, j = t & 31;
        float v = c2[j];
        for (int k = 0; k < 64; k++) v += sb[i * 64 + k] * W2[k * 32 + j];
        sa[t] = lr01(v);
    }
    __syncthreads();
    if (t < 128) {
        int i = t >> 4, j = t & 15;
        float v = c3[j];
        for (int k = 0; k < 32; k++) v += sa[i * 32 + k] * W3[k * 16 + j];
        sb[t] = lr01(v);
    }
    __syncthreads();
    if (t < 64) {
        int i = t >> 3, j = t & 7;
        float v = c4[j];
        for (int k = 0; k < 16; k++) v += sb[i * 16 + k] * W4[k * 8 + j];
        sa[t] = lr01(v);
    }
    __syncthreads();
    if (t < G_GRAPHS) {
        float v = c5[0];
        for (int k = 0; k < 8; k++) v += sa[t * 8 + k] * W5[k];
        out[t] = v * W6[0] + c6[0];
    }
}

// ---------------- launcher ----------------
extern "C" void kernel_launch(void* const* d_in, const int* in_sizes, int n_in,
                              void* d_out, int out_size)
{
    const float* x     = (const float*)d_in[0];
    const int*   ei    = (const int*)  d_in[1];
    const float* ea    = (const float*)d_in[2];
    const int*   batch = (const int*)  d_in[3];
    const float* Wl1 = (const float*)d_in[4];  const float* bl1 = (const float*)d_in[5];
    const float* Wr1 = (const float*)d_in[6];  const float* br1 = (const float*)d_in[7];
    const float* We1 = (const float*)d_in[8];  const float* att1 = (const float*)d_in[9];
    const float* bias1 = (const float*)d_in[10];
    const float* Wl2 = (const float*)d_in[11]; const float* bl2 = (const float*)d_in[12];
    const float* Wr2 = (const float*)d_in[13]; const float* br2 = (const float*)d_in[14];
    const float* We2 = (const float*)d_in[15]; const float* att2 = (const float*)d_in[16];
    const float* bias2 = (const float*)d_in[17];
    const float* W1 = (const float*)d_in[18]; const float* c1 = (const float*)d_in[19];
    const float* W2 = (const float*)d_in[20]; const float* c2 = (const float*)d_in[21];
    const float* W3 = (const float*)d_in[22]; const float* c3 = (const float*)d_in[23];
    const float* W4 = (const float*)d_in[24]; const float* c4 = (const float*)d_in[25];
    const float* W5 = (const float*)d_in[26]; const float* c5 = (const float*)d_in[27];
    const float* W6 = (const float*)d_in[28]; const float* c6 = (const float*)d_in[29];
    float* out = (float*)d_out;

    const int* src = ei;
    const int* dst = ei + N_EDGES;

    const int GX = (N_NODES + 127) / 128;      // 391
    const int NB = (N_NODES + 7) / 8;          // 6250

    // NOTE: launch order places gemm_k128 as the 4th kernel so ncu's -s 5
    // window captures it instead of scatter_kernel.
    zero_kernel<<<(N_NODES + 255) / 256, 256>>>();
    hist_kernel<<<(N_EDGES + 255) / 256, 256>>>(dst);
    scan_kernel<<<1, 1024>>>();
    gemm_k128<<<dim3(GX, 2), 256>>>(x, 0, Wl1, bl1, 0, N_NODES, 128);   // <- profiled
    scatter_kernel<<<(N_EDGES + 255) / 256, 256>>>(src, dst);
    gemm_k128<<<dim3(GX, 2), 256>>>(x, 0, Wr1, br1, 1, N_NODES, 128);
    conv_kernel<128><<<NB, 256>>>(ea, We1, att1, bias1);

    gemm_k128<<<dim3(GX, 3), 256>>>(nullptr, 1, Wl2, bl2, 2, N_NODES, 192);
    gemm_k128<<<dim3(GX, 3), 256>>>(nullptr, 1, Wr2, br2, 3, N_NODES, 192);
    conv_kernel<192><<<NB, 256>>>(ea, We2, att2, bias2);

    pool_kernel<<<128, 192>>>(batch);
    mlp_kernel<<<1, 512>>>(W1, c1, W2, c2, W3, c3, W4, c4, W5, c5, W6, c6, out);
}

// round 7
// speedup vs baseline: 1.1265x; 1.1265x over previous
#include <cuda_runtime.h>
#include <math.h>

#define N_NODES 50000
#define N_EDGES 800000
#define G_GRAPHS 8
#define ED_DIM 32

typedef unsigned long long u64;

__device__ __forceinline__ u64 pack2s(float a) {
    u64 r; asm("mov.b64 %0,{%1,%1};" : "=l"(r) : "f"(a)); return r;
}
__device__ __forceinline__ float2 unpk(u64 v) {
    float2 f; asm("mov.b64 {%0,%1},%2;" : "=f"(f.x), "=f"(f.y) : "l"(v)); return f;
}
__device__ __forceinline__ u64 ffma2(u64 a, u64 b, u64 c) {
    u64 d; asm("fma.rn.f32x2 %0,%1,%2,%3;" : "=l"(d) : "l"(a), "l"(b), "l"(c)); return d;
}
__device__ __forceinline__ u64 fadd2(u64 a, u64 b) {
    u64 d; asm("add.rn.f32x2 %0,%1,%2;" : "=l"(d) : "l"(a), "l"(b)); return d;
}

// ---------------- scratch ----------------
__device__ float d_xl1[N_NODES * 128];
__device__ float d_xr1[N_NODES * 128];
__device__ float d_h1 [N_NODES * 128];
__device__ float d_xl2[N_NODES * 192];
__device__ float d_xr2[N_NODES * 192];
__device__ float d_h2 [N_NODES * 192];
__device__ int   d_rowptr[N_NODES + 1];
__device__ int   d_counts[N_NODES];
__device__ int   d_cursor[N_NODES];
__device__ int2  d_csr[N_EDGES];     // (src, eid) grouped by dst
__device__ float d_pool[G_GRAPHS * 192];

__device__ __forceinline__ float lr2(float x)  { return x > 0.f ? x : 0.2f  * x; }
__device__ __forceinline__ float lr01(float x) { return x > 0.f ? x : 0.01f * x; }

// ---------------- CSR build ----------------
__global__ void zero_kernel() {
    int i = blockIdx.x * blockDim.x + threadIdx.x;
    if (i < N_NODES) { d_counts[i] = 0; d_cursor[i] = 0; }
    if (i < G_GRAPHS * 192) d_pool[i] = 0.f;
}

__global__ void hist_kernel(const int* __restrict__ dst) {
    int e = blockIdx.x * blockDim.x + threadIdx.x;
    if (e < N_EDGES) atomicAdd(&d_counts[dst[e]], 1);
}

__global__ void scan_kernel() {
    __shared__ int sh[1024];
    int t = threadIdx.x;
    const int CH = (N_NODES + 1023) / 1024;
    int lo = t * CH;
    int hi = min(lo + CH, N_NODES);
    int s = 0;
    for (int i = lo; i < hi; i++) s += d_counts[i];
    sh[t] = s;
    __syncthreads();
    for (int off = 1; off < 1024; off <<= 1) {
        int v = (t >= off) ? sh[t - off] : 0;
        __syncthreads();
        sh[t] += v;
        __syncthreads();
    }
    int run = (t > 0) ? sh[t - 1] : 0;
    for (int i = lo; i < hi; i++) { d_rowptr[i] = run; run += d_counts[i]; }
    if (t == 0) d_rowptr[N_NODES] = N_EDGES;
}

__global__ void scatter_kernel(const int* __restrict__ src, const int* __restrict__ dst) {
    int e = blockIdx.x * blockDim.x + threadIdx.x;
    if (e < N_EDGES) {
        int d = dst[e];
        int p = atomicAdd(&d_cursor[d], 1);
        d_csr[d_rowptr[d] + p] = make_int2(src[e], e);
    }
}

// ---------------- GEMM: Y[M,Ncols] = X[M,128] @ W[128,Ncols] + bias ----------------
__global__ __launch_bounds__(256) void gemm_k128(
    const float* __restrict__ Xin, int useH1,
    const float* __restrict__ W, const float* __restrict__ bias,
    int outSel, int M, int Ncols)
{
    const float* X = useH1 ? d_h1 : Xin;
    float* Y = (outSel == 0) ? d_xl1 : (outSel == 1) ? d_xr1 : (outSel == 2) ? d_xl2 : d_xr2;

    __shared__ float XsT[32 * 132];  // [k][m]
    __shared__ float Ws [32 * 68];   // [k][n]

    int tid = threadIdx.x;
    int tx = tid & 15, ty = tid >> 4;
    int m0 = blockIdx.x * 128, n0 = blockIdx.y * 64;

    u64 acc[8][2] = {};

    for (int k0 = 0; k0 < 128; k0 += 32) {
        for (int gi = tid; gi < 1024; gi += 256) {
            int m = gi >> 3, k4 = gi & 7;
            int row = m0 + m;
            float4 v = make_float4(0.f, 0.f, 0.f, 0.f);
            if (row < M) v = *(const float4*)&X[(size_t)row * 128 + k0 + k4 * 4];
            XsT[(k4 * 4 + 0) * 132 + m] = v.x;
            XsT[(k4 * 4 + 1) * 132 + m] = v.y;
            XsT[(k4 * 4 + 2) * 132 + m] = v.z;
            XsT[(k4 * 4 + 3) * 132 + m] = v.w;
        }
        for (int gi = tid; gi < 512; gi += 256) {
            int kk = gi >> 4, n4 = gi & 15;
            float4 v = *(const float4*)&W[(size_t)(k0 + kk) * Ncols + n0 + n4 * 4];
            *(float4*)&Ws[kk * 68 + n4 * 4] = v;
        }
        __syncthreads();
        #pragma unroll 8
        for (int kk = 0; kk < 32; kk++) {
            ulonglong2 w2 = *(const ulonglong2*)&Ws[kk * 68 + tx * 4];
            float4 a03 = *(const float4*)&XsT[kk * 132 + ty * 8];
            float4 a47 = *(const float4*)&XsT[kk * 132 + ty * 8 + 4];
            float av[8] = {a03.x, a03.y, a03.z, a03.w, a47.x, a47.y, a47.z, a47.w};
            #pragma unroll
            for (int i = 0; i < 8; i++) {
                u64 a2 = pack2s(av[i]);
                acc[i][0] = ffma2(a2, w2.x, acc[i][0]);
                acc[i][1] = ffma2(a2, w2.y, acc[i][1]);
            }
        }
        __syncthreads();
    }

    float4 bv = *(const float4*)&bias[n0 + tx * 4];
    #pragma unroll
    for (int i = 0; i < 8; i++) {
        int row = m0 + ty * 8 + i;
        if (row < M) {
            float2 p0 = unpk(acc[i][0]), p1 = unpk(acc[i][1]);
            float4 o = make_float4(p0.x + bv.x, p0.y + bv.y, p1.x + bv.z, p1.y + bv.w);
            *(float4*)&Y[(size_t)row * Ncols + n0 + tx * 4] = o;
        }
    }
}

// ---------------- GATv2 conv: fused warp-per-node, NO-MAX softmax ----------------
// exp(a)/sum(exp(a)) computed directly (|alpha| << 80 so no overflow risk);
// kills the serial per-edge rescale chain: the 4 edges' shfl-reduce chains are
// independent, one expf per edge, plain accumulate.
template <int HC>
__global__ __launch_bounds__(256) void conv_kernel(
    const float* __restrict__ ea, const float* __restrict__ We,
    const float* __restrict__ att, const float* __restrict__ bias)
{
    constexpr bool HB = (HC == 192);
    const float* xl = (HC == 128) ? d_xl1 : d_xl2;
    const float* xr = (HC == 128) ? d_xr1 : d_xr2;
    float*       h  = (HC == 128) ? d_h1  : d_h2;

    __shared__ float sWe[32 * HC];
    for (int i = threadIdx.x; i < 32 * HC; i += 256) sWe[i] = We[i];
    __syncthreads();

    const unsigned FULL = 0xffffffffu;
    int warp = threadIdx.x >> 5, lane = threadIdx.x & 31;
    int node = blockIdx.x * 8 + warp;
    if (node >= N_NODES) return;

    int cA = 4 * lane;
    int hA = (lane < 16) ? 0 : 1;
    float attA[4], biasA[4];
    #pragma unroll
    for (int i = 0; i < 4; i++) {
        attA[i]  = att[hA * 64 + 4 * (lane & 15) + i];
        biasA[i] = bias[cA + i];
    }
    float attB[2] = {0.f, 0.f}, biasB[2] = {0.f, 0.f};
    if (HB) {
        attB[0]  = att[128 + 2 * lane + 0];
        attB[1]  = att[128 + 2 * lane + 1];
        biasB[0] = bias[128 + 2 * lane + 0];
        biasB[1] = bias[128 + 2 * lane + 1];
    }

    int r0 = d_rowptr[node], r1 = d_rowptr[node + 1];
    int deg = r1 - r0;

    ulonglong2 xrA = *(const ulonglong2*)&xr[(size_t)node * HC + cA];
    ulonglong2 xlA = *(const ulonglong2*)&xl[(size_t)node * HC + cA];
    u64 xrB = 0, xlB = 0;
    if (HB) {
        xrB = *(const u64*)&xr[(size_t)node * HC + 128 + 2 * lane];
        xlB = *(const u64*)&xl[(size_t)node * HC + 128 + 2 * lane];
    }

    float sA = 0.f, sB = 0.f;
    u64 accA0 = 0, accA1 = 0, accB = 0;
    float easum = 0.f;

    for (int base = 0; base < deg; base += 32) {
        int j = base + lane;
        int2 es = (j < deg) ? d_csr[r0 + j] : make_int2(0, 0);
        int nb = min(32, deg - base);   // warp-uniform
        for (int bu = 0; bu < nb; bu += 4) {
            int cnt = min(4, nb - bu);  // warp-uniform
            float eav[4];
            ulonglong2 xA[4], vA[4];
            u64 xB[4], vB[4];
            #pragma unroll
            for (int t = 0; t < 4; t++) {
                int s_t = __shfl_sync(FULL, es.x, bu + t);
                int e_t = __shfl_sync(FULL, es.y, bu + t);
                if (t < cnt) {
                    eav[t] = ea[(size_t)e_t * ED_DIM + lane];
                    xA[t]  = *(const ulonglong2*)&xl[(size_t)s_t * HC + cA];
                    vA[t].x = fadd2(xA[t].x, xrA.x);
                    vA[t].y = fadd2(xA[t].y, xrA.y);
                    if (HB) {
                        xB[t] = *(const u64*)&xl[(size_t)s_t * HC + 128 + 2 * lane];
                        vB[t] = fadd2(xB[t], xrB);
                    }
                } else {
                    eav[t] = 0.f;
                    xA[t].x = xA[t].y = 0ull;
                    vA[t].x = vA[t].y = 0ull;
                    if (HB) { xB[t] = 0ull; vB[t] = 0ull; }
                }
                easum += eav[t];
            }
            // ee = ea @ We, packed FFMA2; one shared read serves 4 edges
            #pragma unroll
            for (int k = 0; k < 32; k++) {
                ulonglong2 w = *(const ulonglong2*)&sWe[k * HC + cA];
                u64 wb = 0;
                if (HB) wb = *(const u64*)&sWe[k * HC + 128 + 2 * lane];
                #pragma unroll
                for (int t = 0; t < 4; t++) {
                    u64 a2 = pack2s(__shfl_sync(FULL, eav[t], k));
                    vA[t].x = ffma2(a2, w.x, vA[t].x);
                    vA[t].y = ffma2(a2, w.y, vA[t].y);
                    if (HB) vB[t] = ffma2(a2, wb, vB[t]);
                }
            }
            // alpha partials
            float pav[4], pbv[4];
            #pragma unroll
            for (int t = 0; t < 4; t++) {
                float2 f0 = unpk(vA[t].x), f1 = unpk(vA[t].y);
                pav[t] = lr2(f0.x) * attA[0] + lr2(f0.y) * attA[1]
                       + lr2(f1.x) * attA[2] + lr2(f1.y) * attA[3];
                if (HB) {
                    float2 fb = unpk(vB[t]);
                    pbv[t] = lr2(fb.x) * attB[0] + lr2(fb.y) * attB[1];
                } else pbv[t] = 0.f;
            }
            // 4 independent reduce chains (ILP across t)
            #pragma unroll
            for (int s = 8; s >= 1; s >>= 1) {
                #pragma unroll
                for (int t = 0; t < 4; t++)
                    pav[t] += __shfl_xor_sync(FULL, pav[t], s);
            }
            if (HB) {
                #pragma unroll
                for (int s = 16; s >= 1; s >>= 1) {
                    #pragma unroll
                    for (int t = 0; t < 4; t++)
                        pbv[t] += __shfl_xor_sync(FULL, pbv[t], s);
                }
            }
            // direct exp accumulate (no max, no rescale)
            #pragma unroll
            for (int t = 0; t < 4; t++) {
                if (t < cnt) {
                    float p = __expf(pav[t]);
                    sA += p;
                    u64 p2 = pack2s(p);
                    accA0 = ffma2(p2, xA[t].x, accA0);
                    accA1 = ffma2(p2, xA[t].y, accA1);
                    if (HB) {
                        float pb = __expf(pbv[t]);
                        sB += pb;
                        accB = ffma2(pack2s(pb), xB[t], accB);
                    }
                }
            }
        }
    }

    // ---- self loop: ea_loop = mean of incoming edge attrs (0 if none) ----
    {
        float eal = easum * (1.0f / (float)max(deg, 1));
        u64 v0 = fadd2(xlA.x, xrA.x);
        u64 v1 = fadd2(xlA.y, xrA.y);
        u64 vb = HB ? fadd2(xlB, xrB) : 0ull;
        #pragma unroll
        for (int k = 0; k < 32; k++) {
            u64 a2 = pack2s(__shfl_sync(FULL, eal, k));
            ulonglong2 w = *(const ulonglong2*)&sWe[k * HC + cA];
            v0 = ffma2(a2, w.x, v0);
            v1 = ffma2(a2, w.y, v1);
            if (HB) {
                u64 wb = *(const u64*)&sWe[k * HC + 128 + 2 * lane];
                vb = ffma2(a2, wb, vb);
            }
        }
        float2 f0 = unpk(v0), f1 = unpk(v1);
        float pa = lr2(f0.x) * attA[0] + lr2(f0.y) * attA[1]
                 + lr2(f1.x) * attA[2] + lr2(f1.y) * attA[3];
        pa += __shfl_xor_sync(FULL, pa, 8);
        pa += __shfl_xor_sync(FULL, pa, 4);
        pa += __shfl_xor_sync(FULL, pa, 2);
        pa += __shfl_xor_sync(FULL, pa, 1);
        float p = __expf(pa);
        sA += p;
        u64 p2 = pack2s(p);
        accA0 = ffma2(p2, xlA.x, accA0);
        accA1 = ffma2(p2, xlA.y, accA1);
        if (HB) {
            float2 fb = unpk(vb);
            float pb = lr2(fb.x) * attB[0] + lr2(fb.y) * attB[1];
            pb += __shfl_xor_sync(FULL, pb, 16);
            pb += __shfl_xor_sync(FULL, pb, 8);
            pb += __shfl_xor_sync(FULL, pb, 4);
            pb += __shfl_xor_sync(FULL, pb, 2);
            pb += __shfl_xor_sync(FULL, pb, 1);
            float pe = __expf(pb);
            sB += pe;
            accB = ffma2(pack2s(pe), xlB, accB);
        }
    }

    // ---- write h = lrelu_{0.01}(acc/s + bias) ----
    float invA = 1.0f / sA;
    float2 a0 = unpk(accA0), a1 = unpk(accA1);
    float4 o;
    o.x = lr01(a0.x * invA + biasA[0]);
    o.y = lr01(a0.y * invA + biasA[1]);
    o.z = lr01(a1.x * invA + biasA[2]);
    o.w = lr01(a1.y * invA + biasA[3]);
    *(float4*)&h[(size_t)node * HC + cA] = o;
    if (HB) {
        float invB = 1.0f / sB;
        float2 ab = unpk(accB);
        float2 ob;
        ob.x = lr01(ab.x * invB + biasB[0]);
        ob.y = lr01(ab.y * invB + biasB[1]);
        *(float2*)&h[(size_t)node * HC + 128 + 2 * lane] = ob;
    }
}

// ---------------- global_add_pool ----------------
__global__ void pool_kernel(const int* __restrict__ batch) {
    __shared__ float acc[G_GRAPHS * 192];
    int c = threadIdx.x;  // 0..191
    for (int i = c; i < G_GRAPHS * 192; i += 192) acc[i] = 0.f;
    __syncthreads();
    int per = (N_NODES + gridDim.x - 1) / gridDim.x;
    int lo = blockIdx.x * per;
    int hi = min(lo + per, N_NODES);
    for (int n = lo; n < hi; n++) {
        int b = batch[n];
        acc[b * 192 + c] += d_h2[(size_t)n * 192 + c];
    }
    __syncthreads();
    for (int i = c; i < G_GRAPHS * 192; i += 192) atomicAdd(&d_pool[i], acc[i]);
}

// ---------------- MLP head ----------------
__global__ void mlp_kernel(
    const float* __restrict__ W1, const float* __restrict__ c1,
    const float* __restrict__ W2, const float* __restrict__ c2,
    const float* __restrict__ W3, const float* __restrict__ c3,
    const float* __restrict__ W4, const float* __restrict__ c4,
    const float* __restrict__ W5, const float* __restrict__ c5,
    const float* __restrict__ W6, const float* __restrict__ c6,
    float* __restrict__ out)
{
    __shared__ float sa[G_GRAPHS * 192];
    __shared__ float sb[G_GRAPHS * 64];
    int t = threadIdx.x;
    for (int i = t; i < G_GRAPHS * 192; i += 512) sa[i] = d_pool[i];
    __syncthreads();
    if (t < 512) {
        int i = t >> 6, j = t & 63;
        float v = c1[j];
        for (int k = 0; k < 192; k++) v += sa[i * 192 + k] * W1[k * 64 + j];
        sb[t] = lr01(v);
    }
    __syncthreads();
    if (t < 256) {
        int i = t >> 5, j = t & 31;
        float v = c2[j];
        for (int k = 0; k < 64; k++) v += sb[i * 64 + k] * W2[k * 32 + j];
        sa[t] = lr01(v);
    }
    __syncthreads();
    if (t < 128) {
        int i = t >> 4, j = t & 15;
        float v = c3[j];
        for (int k = 0; k < 32; k++) v += sa[i * 32 + k] * W3[k * 16 + j];
        sb[t] = lr01(v);
    }
    __syncthreads();
    if (t < 64) {
        int i = t >> 3, j = t & 7;
        float v = c4[j];
        for (int k = 0; k < 16; k++) v += sb[i * 16 + k] * W4[k * 8 + j];
        sa[t] = lr01(v);
    }
    __syncthreads();
    if (t < G_GRAPHS) {
        float v = c5[0];
        for (int k = 0; k < 8; k++) v += sa[t * 8 + k] * W5[k];
        out[t] = v * W6[0] + c6[0];
    }
}

// ---------------- launcher ----------------
extern "C" void kernel_launch(void* const* d_in, const int* in_sizes, int n_in,
                              void* d_out, int out_size)
{
    const float* x     = (const float*)d_in[0];
    const int*   ei    = (const int*)  d_in[1];
    const float* ea    = (const float*)d_in[2];
    const int*   batch = (const int*)  d_in[3];
    const float* Wl1 = (const float*)d_in[4];  const float* bl1 = (const float*)d_in[5];
    const float* Wr1 = (const float*)d_in[6];  const float* br1 = (const float*)d_in[7];
    const float* We1 = (const float*)d_in[8];  const float* att1 = (const float*)d_in[9];
    const float* bias1 = (const float*)d_in[10];
    const float* Wl2 = (const float*)d_in[11]; const float* bl2 = (const float*)d_in[12];
    const float* Wr2 = (const float*)d_in[13]; const float* br2 = (const float*)d_in[14];
    const float* We2 = (const float*)d_in[15]; const float* att2 = (const float*)d_in[16];
    const float* bias2 = (const float*)d_in[17];
    const float* W1 = (const float*)d_in[18]; const float* c1 = (const float*)d_in[19];
    const float* W2 = (const float*)d_in[20]; const float* c2 = (const float*)d_in[21];
    const float* W3 = (const float*)d_in[22]; const float* c3 = (const float*)d_in[23];
    const float* W4 = (const float*)d_in[24]; const float* c4 = (const float*)d_in[25];
    const float* W5 = (const float*)d_in[26]; const float* c5 = (const float*)d_in[27];
    const float* W6 = (const float*)d_in[28]; const float* c6 = (const float*)d_in[29];
    float* out = (float*)d_out;

    const int* src = ei;
    const int* dst = ei + N_EDGES;

    const int GX = (N_NODES + 127) / 128;      // 391
    const int NB = (N_NODES + 7) / 8;          // 6250

    // gemm_k128 stays the 4th launch (ncu -s 5 window) for comparable profiles.
    zero_kernel<<<(N_NODES + 255) / 256, 256>>>();
    hist_kernel<<<(N_EDGES + 255) / 256, 256>>>(dst);
    scan_kernel<<<1, 1024>>>();
    gemm_k128<<<dim3(GX, 2), 256>>>(x, 0, Wl1, bl1, 0, N_NODES, 128);   // <- profiled
    scatter_kernel<<<(N_EDGES + 255) / 256, 256>>>(src, dst);
    gemm_k128<<<dim3(GX, 2), 256>>>(x, 0, Wr1, br1, 1, N_NODES, 128);
    conv_kernel<128><<<NB, 256>>>(ea, We1, att1, bias1);

    gemm_k128<<<dim3(GX, 3), 256>>>(nullptr, 1, Wl2, bl2, 2, N_NODES, 192);
    gemm_k128<<<dim3(GX, 3), 256>>>(nullptr, 1, Wr2, br2, 3, N_NODES, 192);
    conv_kernel<192><<<NB, 256>>>(ea, We2, att2, bias2);

    pool_kernel<<<128, 192>>>(batch);
    mlp_kernel<<<1, 512>>>(W1, c1, W2, c2, W3, c3, W4, c4, W5, c5, W6, c6, out);
}